// round 2
// baseline (speedup 1.0000x reference)
#include <cuda_runtime.h>

// rdf_40338332844610 — batched RDF with Gaussian smearing, B=4, N=600, 64 bins.
// Output layout (guessed from reference tuple (BINS[65], rdf[64])): 129 floats.
// Finalize kernel adapts if out_size == 64 (rdf only).

#define NATOMS 600
#define NBATCH 4
#define NBINS  64
#define TPB    128
#define HSTRIDE 129            // TPB+1 padding -> conflict-free columns

// Constants (double-derived, see analysis):
//   w      = 7.5/63,  INV_W = 8.4
//   G      = -0.5/w^2 ;  2*G*w^2 = -1 exactly -> geometric ratio e^-1
//   CUTOFF_ADJ = 7.5 + 2*(7.5/64) = 7.734375 (exact fp32)
//   CUT2   = 7.734375^2 = 59.820556640625 (exact fp32)
#define LBOX   20.0f
#define INVL   0.05f
#define CUT2   59.820556640625f
#define INV_W  8.4f
#define EINV   0.36787944117144233f

__device__ float g_hist[NBINS];

__global__ void zero_kernel() {
    if (threadIdx.x < NBINS) g_hist[threadIdx.x] = 0.0f;
}

__global__ __launch_bounds__(TPB) void hist_kernel(const float* __restrict__ xyz) {
    __shared__ float spos[NATOMS * 3];            // 7.2 KB
    __shared__ float shist[NBINS * HSTRIDE];      // 33.0 KB, per-thread columns

    const int tid = threadIdx.x;
    const int b   = blockIdx.y;

    // Stage this batch's positions into shared
    const float* base = xyz + (size_t)b * NATOMS * 3;
    for (int k = tid; k < NATOMS * 3; k += TPB) spos[k] = base[k];
    // Zero private histogram column (pad slot k*129+128 never touched)
    #pragma unroll
    for (int k = 0; k < NBINS; k++) shist[k * HSTRIDE + tid] = 0.0f;
    __syncthreads();

    const int warp = tid >> 5;
    const int lane = tid & 31;
    const int i = blockIdx.x * 4 + warp;          // gridDim.x = 150 -> i in [0,600)

    const float xi = spos[3 * i + 0];
    const float yi = spos[3 * i + 1];
    const float zi = spos[3 * i + 2];
    float* mh = shist + tid;                      // my column, stride HSTRIDE per bin

    for (int j = lane; j < NATOMS; j += 32) {
        float dx = spos[3 * j + 0] - xi;
        float dy = spos[3 * j + 1] - yi;
        float dz = spos[3 * j + 2] - zi;
        // minimum-image wrap into [-L/2, L/2)  (matches reference offsets)
        dx -= LBOX * floorf(dx * INVL + 0.5f);
        dy -= LBOX * floorf(dy * INVL + 0.5f);
        dz -= LBOX * floorf(dz * INVL + 0.5f);
        float dsq = dx * dx + dy * dy + dz * dz;

        if (j != i && dsq < CUT2 && dsq != 0.0f) {
            float r  = sqrtf(dsq);
            float jr = r * INV_W;                 // r in bin-width units
            int j0 = __float2int_rn(jr);
            if (j0 > 63) j0 = 63;
            float t  = jr - (float)j0;            // |t|<=0.5 except clamped (<~2)

            float h0 = __expf(-0.5f * t * t);     // value at anchor bin
            mh[j0 * HSTRIDE] += h0;

            float ru = __expf(t - 0.5f);          // first up-ratio
            float rd = EINV / ru;                 // first down-ratio = e^(-t-0.5)

            // upward bins: h_{k+1} = h_k * ratio, ratio *= e^-1
            {
                float h = h0, rr = ru;
                int kmax = min(63, j0 + 6);
                for (int k = j0 + 1; k <= kmax; k++) {
                    h *= rr;
                    mh[k * HSTRIDE] += h;
                    rr *= EINV;
                }
            }
            // downward bins
            {
                float h = h0, rr = rd;
                int kmin = max(0, j0 - 6);
                for (int k = j0 - 1; k >= kmin; k--) {
                    h *= rr;
                    mh[k * HSTRIDE] += h;
                    rr *= EINV;
                }
            }
        }
    }
    __syncthreads();

    // Reduce 128 columns per bin; padded stride keeps lanes conflict-free.
    if (tid < NBINS) {
        float s = 0.0f;
        const float* row = shist + tid * HSTRIDE;
        #pragma unroll 8
        for (int k = 0; k < TPB; k++) s += row[k];
        atomicAdd(&g_hist[tid], s);
    }
}

__global__ void finalize_kernel(float* __restrict__ out, int out_size) {
    __shared__ float sc[NBINS];
    __shared__ float stot;
    const int t = threadIdx.x;

    float c = 0.0f;
    if (t < NBINS) {
        c = g_hist[t];
        sc[t] = c;
    }
    __syncthreads();
    if (t == 0) {
        float s = 0.0f;
        #pragma unroll
        for (int k = 0; k < NBINS; k++) s += sc[k];
        stot = s;
    }
    __syncthreads();
    const float total = stot;

    const float STEP = 0.1171875f;                  // 7.5/64, exact
    const bool full = (out_size >= 129);
    if (full) {
        for (int k = t; k < NBINS + 1; k += blockDim.x)
            out[k] = STEP * (float)k;               // BINS (exact multiples)
    }
    if (t < NBINS) {
        float b0 = STEP * (float)t;
        float b1 = STEP * (float)(t + 1);
        float d3  = b1 * b1 * b1 - b0 * b0 * b0;
        float vol = 4.18879020478639098f * d3;      // 4*pi/3 * (b1^3-b0^3)
        const float POW3 = 3701.3969421386719f;     // (2*7.734375)^3
        float denom = 2.0f * vol / POW3;
        float rdf = (c / total) / denom;
        out[(full ? NBINS + 1 : 0) + t] = rdf;
    }
}

extern "C" void kernel_launch(void* const* d_in, const int* in_sizes, int n_in,
                              void* d_out, int out_size) {
    const float* xyz = (const float*)d_in[0];
    float* out = (float*)d_out;

    zero_kernel<<<1, 64>>>();
    dim3 grid(NATOMS / 4, NBATCH);                  // 150 x 4 blocks, 4 warps each
    hist_kernel<<<grid, TPB>>>(xyz);
    finalize_kernel<<<1, 128>>>(out, out_size);
}

// round 3
// speedup vs baseline: 1.1146x; 1.1146x over previous
#include <cuda_runtime.h>

// rdf_40338332844610 — batched RDF + Gaussian smear. B=4, N=600, 64 bins.
// Single fused kernel: triangular (j>i) pair loop with balanced (a, 599-a)
// warp pairing, per-thread smem histogram columns, last-block finalize via
// ticket + threadfence. Normalization makes the 2x symmetry factor cancel.

#define NATOMS 600
#define NBATCH 4
#define NBINS  64
#define TPB    128
#define HSTRIDE 129              // TPB+1 -> conflict-free columns
#define BLOCKS_X 75              // 75 blocks * 4 warps = 300 warp-tasks/batch
#define TOTAL_BLOCKS (BLOCKS_X * NBATCH)
#define WINDOW 5

// exact-fp32 constants (see R1 analysis):
//   w = 7.5/63, INV_W = 8.4, 2*|G|*w^2 = 1 exactly -> geometric ratio e^-1
//   CUTOFF_ADJ = 7.734375, CUT2 = 59.820556640625
#define LBOX 20.0f
#define INVL 0.05f
#define CUT2 59.820556640625f
#define INV_W 8.4f
#define EINV 0.36787944117144233f

__device__ float g_hist[NBINS];          // zero at load; last block re-zeros
__device__ unsigned int g_ticket;        // ditto

__global__ __launch_bounds__(TPB) void rdf_fused_kernel(const float* __restrict__ xyz,
                                                        float* __restrict__ out,
                                                        int out_size) {
    __shared__ float4 spos[NATOMS];               // 9.6 KB
    __shared__ float  shist[NBINS * HSTRIDE];     // 33.0 KB
    __shared__ float  sc[NBINS];
    __shared__ float  stot;
    __shared__ bool   s_last;

    const int tid = threadIdx.x;
    const int b   = blockIdx.y;

    // stage positions (packed float4 for single LDS.128 per neighbor)
    const float* base = xyz + (size_t)b * NATOMS * 3;
    for (int k = tid; k < NATOMS; k += TPB)
        spos[k] = make_float4(base[3 * k], base[3 * k + 1], base[3 * k + 2], 0.0f);
    #pragma unroll
    for (int k = 0; k < NBINS; k++) shist[k * HSTRIDE + tid] = 0.0f;
    __syncthreads();

    const int warp = tid >> 5;
    const int lane = tid & 31;
    const int a  = blockIdx.x * 4 + warp;         // [0, 300)
    const int c1 = 599 - a;                       // seg-1 count (center a)
    const float4 p1 = spos[a];
    const float4 p2 = spos[599 - a];
    float* mh = shist + tid;

    // combined triangular loop: exactly 599 m-values per warp (balanced)
    for (int m = lane; m < 599; m += 32) {
        const bool seg2 = (m >= c1);
        const int j = seg2 ? (m + 1) : (a + 1 + m);
        const float4 pc = seg2 ? p2 : p1;
        const float4 pj = spos[j];
        float dx = pj.x - pc.x;
        float dy = pj.y - pc.y;
        float dz = pj.z - pc.z;
        // min-image wrap; floor(x+0.5) matches reference boundary semantics
        dx -= LBOX * floorf(dx * INVL + 0.5f);
        dy -= LBOX * floorf(dy * INVL + 0.5f);
        dz -= LBOX * floorf(dz * INVL + 0.5f);
        const float dsq = dx * dx + dy * dy + dz * dz;

        if (dsq < CUT2 && dsq != 0.0f) {
            const float r  = sqrtf(dsq);
            const float jr = r * INV_W;
            int j0 = __float2int_rn(jr);
            if (j0 > 63) j0 = 63;
            const float t = jr - (float)j0;

            const float h0 = __expf(-0.5f * t * t);
            mh[j0 * HSTRIDE] += h0;

            const float ru = __expf(t - 0.5f);          // first up-ratio
            const float rd = __fdividef(EINV, ru);      // first down-ratio

            {   // upward: h_{k+1} = h_k * rr, rr *= e^-1
                float h = h0, rr = ru;
                const int kmax = min(63, j0 + WINDOW);
                for (int k = j0 + 1; k <= kmax; k++) {
                    h *= rr;
                    mh[k * HSTRIDE] += h;
                    rr *= EINV;
                }
            }
            {   // downward
                float h = h0, rr = rd;
                const int kmin = max(0, j0 - WINDOW);
                for (int k = j0 - 1; k >= kmin; k--) {
                    h *= rr;
                    mh[k * HSTRIDE] += h;
                    rr *= EINV;
                }
            }
        }
    }
    __syncthreads();

    // per-block reduce: thread t sums half of bin (t&63)'s 128 columns
    {
        const int bin  = tid & 63;
        const int half = tid >> 6;
        const float* row = shist + bin * HSTRIDE + half * 64;
        float s = 0.0f;
        #pragma unroll 8
        for (int k = 0; k < 64; k++) s += row[k];
        atomicAdd(&g_hist[bin], s);
    }
    __syncthreads();

    // ticket: last block finalizes
    if (tid == 0) {
        __threadfence();
        unsigned int prev = atomicAdd(&g_ticket, 1u);
        s_last = (prev == (unsigned int)(TOTAL_BLOCKS - 1));
    }
    __syncthreads();
    if (!s_last) return;

    __threadfence();
    float c = 0.0f;
    if (tid < NBINS) {
        c = __ldcg(&g_hist[tid]);
        sc[tid] = c;
    }
    __syncthreads();
    if (tid == 0) {
        float s = 0.0f;
        #pragma unroll
        for (int k = 0; k < NBINS; k++) s += sc[k];
        stot = s;
    }
    __syncthreads();
    const float total = stot;

    const float STEP = 0.1171875f;                // 7.5/64, exact fp32
    const bool full = (out_size >= 2 * NBINS + 1);
    if (full) {
        for (int k = tid; k < NBINS + 1; k += TPB)
            out[k] = STEP * (float)k;             // BINS edges (exact)
    }
    if (tid < NBINS) {
        const float b0 = STEP * (float)tid;
        const float b1 = STEP * (float)(tid + 1);
        const float d3 = b1 * b1 * b1 - b0 * b0 * b0;
        const float vol = 4.18879020478639098f * d3;     // 4pi/3 * (b1^3-b0^3)
        const float POW3 = 3701.3969421386719f;          // (2*7.734375)^3
        const float denom = 2.0f * vol / POW3;
        out[(full ? NBINS + 1 : 0) + tid] = (c / total) / denom;
        // reset accumulators for the next graph replay (determinism)
        g_hist[tid] = 0.0f;
    }
    if (tid == 0) g_ticket = 0u;
}

extern "C" void kernel_launch(void* const* d_in, const int* in_sizes, int n_in,
                              void* d_out, int out_size) {
    const float* xyz = (const float*)d_in[0];
    float* out = (float*)d_out;
    dim3 grid(BLOCKS_X, NBATCH);                  // 300 blocks, 128 thr each
    rdf_fused_kernel<<<grid, TPB>>>(xyz, out, out_size);
}

// round 5
// speedup vs baseline: 1.2162x; 1.0912x over previous
#include <cuda_runtime.h>

// rdf_40338332844610 — batched RDF + Gaussian smear. B=4, N=600, 64 bins.
// Single fused kernel: triangular (j>i) pair loop with balanced (a, 599-a)
// warp pairing, per-thread smem histogram columns, last-block finalize via
// ticket + threadfence. Normalization makes the 2x symmetry factor cancel.

#define NATOMS 600
#define NBATCH 4
#define NBINS  64
#define TPB    128
#define HSTRIDE 129              // TPB+1 -> conflict-free columns
#define BLOCKS_X 75              // 75 blocks * 4 warps = 300 warp-tasks/batch
#define TOTAL_BLOCKS (BLOCKS_X * NBATCH)
#define WINDOW 5

// exact-fp32 constants (see R1 analysis):
//   w = 7.5/63, INV_W = 8.4, 2*|G|*w^2 = 1 exactly -> geometric ratio e^-1
//   CUTOFF_ADJ = 7.734375, CUT2 = 59.820556640625
#define LBOX 20.0f
#define INVL 0.05f
#define CUT2 59.820556640625f
#define INV_W 8.4f
#define EINV 0.36787944117144233f

__device__ float g_hist[NBINS];          // zero at load; last block re-zeros
__device__ unsigned int g_ticket;        // ditto

__global__ __launch_bounds__(TPB) void rdf_fused_kernel(const float* __restrict__ xyz,
                                                        float* __restrict__ out,
                                                        int out_size) {
    __shared__ float4 spos[NATOMS];               // 9.6 KB
    __shared__ float  shist[NBINS * HSTRIDE];     // 33.0 KB
    __shared__ float  sc[NBINS];
    __shared__ float  stot;
    __shared__ bool   s_last;

    const int tid = threadIdx.x;
    const int b   = blockIdx.y;

    // stage positions (packed float4 for single LDS.128 per neighbor)
    const float* base = xyz + (size_t)b * NATOMS * 3;
    for (int k = tid; k < NATOMS; k += TPB)
        spos[k] = make_float4(base[3 * k], base[3 * k + 1], base[3 * k + 2], 0.0f);
    #pragma unroll
    for (int k = 0; k < NBINS; k++) shist[k * HSTRIDE + tid] = 0.0f;
    __syncthreads();

    const int warp = tid >> 5;
    const int lane = tid & 31;
    const int a  = blockIdx.x * 4 + warp;         // [0, 300)
    const int c1 = 599 - a;                       // seg-1 count (center a)
    const float4 p1 = spos[a];
    const float4 p2 = spos[599 - a];
    float* mh = shist + tid;

    // combined triangular loop: exactly 599 m-values per warp (balanced)
    for (int m = lane; m < 599; m += 32) {
        const bool seg2 = (m >= c1);
        const int j = seg2 ? (m + 1) : (a + 1 + m);
        const float4 pc = seg2 ? p2 : p1;
        const float4 pj = spos[j];
        float dx = pj.x - pc.x;
        float dy = pj.y - pc.y;
        float dz = pj.z - pc.z;
        // min-image wrap; floor(x+0.5) matches reference boundary semantics
        dx -= LBOX * floorf(dx * INVL + 0.5f);
        dy -= LBOX * floorf(dy * INVL + 0.5f);
        dz -= LBOX * floorf(dz * INVL + 0.5f);
        const float dsq = dx * dx + dy * dy + dz * dz;

        if (dsq < CUT2 && dsq != 0.0f) {
            const float r  = sqrtf(dsq);
            const float jr = r * INV_W;
            int j0 = __float2int_rn(jr);
            if (j0 > 63) j0 = 63;
            const float t = jr - (float)j0;

            const float h0 = __expf(-0.5f * t * t);
            mh[j0 * HSTRIDE] += h0;

            const float ru = __expf(t - 0.5f);          // first up-ratio
            const float rd = __fdividef(EINV, ru);      // first down-ratio

            {   // upward: h_{k+1} = h_k * rr, rr *= e^-1
                float h = h0, rr = ru;
                const int kmax = min(63, j0 + WINDOW);
                for (int k = j0 + 1; k <= kmax; k++) {
                    h *= rr;
                    mh[k * HSTRIDE] += h;
                    rr *= EINV;
                }
            }
            {   // downward
                float h = h0, rr = rd;
                const int kmin = max(0, j0 - WINDOW);
                for (int k = j0 - 1; k >= kmin; k--) {
                    h *= rr;
                    mh[k * HSTRIDE] += h;
                    rr *= EINV;
                }
            }
        }
    }
    __syncthreads();

    // per-block reduce: thread t sums half of bin (t&63)'s 128 columns
    {
        const int bin  = tid & 63;
        const int half = tid >> 6;
        const float* row = shist + bin * HSTRIDE + half * 64;
        float s = 0.0f;
        #pragma unroll 8
        for (int k = 0; k < 64; k++) s += row[k];
        atomicAdd(&g_hist[bin], s);
    }
    __syncthreads();

    // ticket: last block finalizes
    if (tid == 0) {
        __threadfence();
        unsigned int prev = atomicAdd(&g_ticket, 1u);
        s_last = (prev == (unsigned int)(TOTAL_BLOCKS - 1));
    }
    __syncthreads();
    if (!s_last) return;

    __threadfence();
    float c = 0.0f;
    if (tid < NBINS) {
        c = __ldcg(&g_hist[tid]);
        sc[tid] = c;
    }
    __syncthreads();
    if (tid == 0) {
        float s = 0.0f;
        #pragma unroll
        for (int k = 0; k < NBINS; k++) s += sc[k];
        stot = s;
    }
    __syncthreads();
    const float total = stot;

    const float STEP = 0.1171875f;                // 7.5/64, exact fp32
    const bool full = (out_size >= 2 * NBINS + 1);
    if (full) {
        for (int k = tid; k < NBINS + 1; k += TPB)
            out[k] = STEP * (float)k;             // BINS edges (exact)
    }
    if (tid < NBINS) {
        const float b0 = STEP * (float)tid;
        const float b1 = STEP * (float)(tid + 1);
        const float d3 = b1 * b1 * b1 - b0 * b0 * b0;
        const float vol = 4.18879020478639098f * d3;     // 4pi/3 * (b1^3-b0^3)
        const float POW3 = 3701.3969421386719f;          // (2*7.734375)^3
        const float denom = 2.0f * vol / POW3;
        out[(full ? NBINS + 1 : 0) + tid] = (c / total) / denom;
        // reset accumulators for the next graph replay (determinism)
        g_hist[tid] = 0.0f;
    }
    if (tid == 0) g_ticket = 0u;
}

extern "C" void kernel_launch(void* const* d_in, const int* in_sizes, int n_in,
                              void* d_out, int out_size) {
    const float* xyz = (const float*)d_in[0];
    float* out = (float*)d_out;
    dim3 grid(BLOCKS_X, NBATCH);                  // 300 blocks, 128 thr each
    rdf_fused_kernel<<<grid, TPB>>>(xyz, out, out_size);
}

// round 7
// speedup vs baseline: 1.3636x; 1.1212x over previous
#include <cuda_runtime.h>

// rdf_40338332844610 — batched RDF + Gaussian smear. B=4, N=600, 64 bins.
// R5: 2x parallelism (each center-pair split over 2 warp-tasks -> 600 blocks),
// fixed-trip fully-unrolled +/-5 smear with interleaved up/down chains.

#define NATOMS 600
#define NBATCH 4
#define NBINS  64
#define TPB    128
#define HSTRIDE 129              // TPB+1 -> conflict-free columns
#define BLOCKS_X 150             // 150 blocks * 4 warp-tasks = 600 tasks/batch
#define TOTAL_BLOCKS (BLOCKS_X * NBATCH)
#define WINDOW 5

// exact-fp32 constants:
//   w = 7.5/63, INV_W = 8.4, 2*|G|*w^2 = 1 exactly -> geometric ratio e^-1
//   CUTOFF_ADJ = 7.734375, CUT2 = 59.820556640625
#define LBOX 20.0f
#define INVL 0.05f
#define CUT2 59.820556640625f
#define INV_W 8.4f
#define EINV 0.36787944117144233f

__device__ float g_hist[NBINS];          // zero at load; finalizer re-zeros
__device__ unsigned int g_ticket;

__global__ __launch_bounds__(TPB) void rdf_fused_kernel(const float* __restrict__ xyz,
                                                        float* __restrict__ out,
                                                        int out_size) {
    __shared__ float4 spos[NATOMS];               // 9.6 KB
    __shared__ float  shist[NBINS * HSTRIDE];     // 33.0 KB
    __shared__ float  sc[NBINS];
    __shared__ float  stot;
    __shared__ bool   s_last;

    const int tid = threadIdx.x;
    const int b   = blockIdx.y;

    // stage positions
    const float* base = xyz + (size_t)b * NATOMS * 3;
    for (int k = tid; k < NATOMS; k += TPB)
        spos[k] = make_float4(base[3 * k], base[3 * k + 1], base[3 * k + 2], 0.0f);
    #pragma unroll
    for (int k = 0; k < NBINS; k++) shist[k * HSTRIDE + tid] = 0.0f;
    __syncthreads();

    const int warp = tid >> 5;
    const int lane = tid & 31;
    const int task = blockIdx.x * 4 + warp;       // [0, 600)
    const int a    = task >> 1;                   // center-pair id [0, 300)
    const int half = task & 1;                    // which 32-stride half
    const int c1 = 599 - a;                       // seg-1 count (center a)
    const float4 p1 = spos[a];
    const float4 p2 = spos[599 - a];
    float* mh = shist + tid;

    // triangular loop, split: ~9.5 m-values per warp, balanced across tasks
    for (int m = lane + 32 * half; m < 599; m += 64) {
        const bool seg2 = (m >= c1);
        const int j = seg2 ? (m + 1) : (a + 1 + m);
        const float4 pc = seg2 ? p2 : p1;
        const float4 pj = spos[j];
        float dx = pj.x - pc.x;
        float dy = pj.y - pc.y;
        float dz = pj.z - pc.z;
        dx -= LBOX * floorf(dx * INVL + 0.5f);
        dy -= LBOX * floorf(dy * INVL + 0.5f);
        dz -= LBOX * floorf(dz * INVL + 0.5f);
        const float dsq = dx * dx + dy * dy + dz * dz;

        if (dsq < CUT2 && dsq != 0.0f) {
            const float r  = sqrtf(dsq);
            const float jr = r * INV_W;
            int j0 = __float2int_rn(jr);
            if (j0 > 63) j0 = 63;
            const float t = jr - (float)j0;

            const float h0 = __expf(-0.5f * t * t);
            mh[j0 * HSTRIDE] += h0;

            // geometric recurrences: after s steps h = exp(-(t +/- s)^2 / 2), exact
            float hu = h0, cu = __expf(t - 0.5f);
            float hd = h0, cd = __fdividef(EINV, cu);
            #pragma unroll
            for (int s = 1; s <= WINDOW; s++) {
                hu *= cu; cu *= EINV;
                hd *= cd; cd *= EINV;
                const int ku = j0 + s;
                const int kd = j0 - s;
                if (ku <= 63) mh[ku * HSTRIDE] += hu;
                if (kd >= 0)  mh[kd * HSTRIDE] += hd;
            }
        }
    }
    __syncthreads();

    // per-block reduce: thread t sums half of bin (t&63)'s 128 columns
    {
        const int bin   = tid & 63;
        const int halfc = tid >> 6;
        const float* row = shist + bin * HSTRIDE + halfc * 64;
        float s = 0.0f;
        #pragma unroll 8
        for (int k = 0; k < 64; k++) s += row[k];
        atomicAdd(&g_hist[bin], s);
    }
    __syncthreads();

    if (tid == 0) {
        __threadfence();
        unsigned int prev = atomicAdd(&g_ticket, 1u);
        s_last = (prev == (unsigned int)(TOTAL_BLOCKS - 1));
    }
    __syncthreads();
    if (!s_last) return;

    __threadfence();
    float c = 0.0f;
    if (tid < NBINS) {
        c = __ldcg(&g_hist[tid]);
        sc[tid] = c;
    }
    __syncthreads();
    if (tid == 0) {
        float s = 0.0f;
        #pragma unroll
        for (int k = 0; k < NBINS; k++) s += sc[k];
        stot = s;
    }
    __syncthreads();
    const float total = stot;

    const float STEP = 0.1171875f;                // 7.5/64, exact fp32
    const bool full = (out_size >= 2 * NBINS + 1);
    if (full) {
        for (int k = tid; k < NBINS + 1; k += TPB)
            out[k] = STEP * (float)k;             // BINS edges (exact)
    }
    if (tid < NBINS) {
        const float b0 = STEP * (float)tid;
        const float b1 = STEP * (float)(tid + 1);
        const float d3 = b1 * b1 * b1 - b0 * b0 * b0;
        const float vol = 4.18879020478639098f * d3;     // 4pi/3 * (b1^3-b0^3)
        const float POW3 = 3701.3969421386719f;          // (2*7.734375)^3
        const float denom = 2.0f * vol / POW3;
        out[(full ? NBINS + 1 : 0) + tid] = (c / total) / denom;
        g_hist[tid] = 0.0f;                       // reset for next graph replay
    }
    if (tid == 0) g_ticket = 0u;
}

extern "C" void kernel_launch(void* const* d_in, const int* in_sizes, int n_in,
                              void* d_out, int out_size) {
    const float* xyz = (const float*)d_in[0];
    float* out = (float*)d_out;
    dim3 grid(BLOCKS_X, NBATCH);                  // 600 blocks, 128 thr each
    rdf_fused_kernel<<<grid, TPB>>>(xyz, out, out_size);
}